// round 8
// baseline (speedup 1.0000x reference)
#include <cuda_runtime.h>
#include <cstdint>

#define BB 32
#define SS 2048
#define DD 64

// ===================== tf32 split + mma.sync helpers ========================
// split x into hi + lo, both exactly representable in tf32 (rna rounding).
// hi+lo captures ~21 mantissa bits -> product error ~2^-21 (fp32-class).
__device__ __forceinline__ float2 split_tf32(float x) {
    uint32_t h;
    asm("cvt.rna.tf32.f32 %0, %1;" : "=r"(h) : "f"(x));
    float hf = __uint_as_float(h);
    float rem = x - hf;
    uint32_t l;
    asm("cvt.rna.tf32.f32 %0, %1;" : "=r"(l) : "f"(rem));
    return make_float2(hf, __uint_as_float(l));
}

// D += A(16x8 tf32) * B(8x8 tf32), m16n8k8, A row-major frag, B col-major frag
__device__ __forceinline__ void mma8(float* c, float4 a, float2 b) {
    asm volatile(
        "mma.sync.aligned.m16n8k8.row.col.f32.tf32.tf32.f32 "
        "{%0,%1,%2,%3}, {%4,%5,%6,%7}, {%8,%9}, {%0,%1,%2,%3};"
        : "+f"(c[0]), "+f"(c[1]), "+f"(c[2]), "+f"(c[3])
        : "r"(__float_as_uint(a.x)), "r"(__float_as_uint(a.y)),
          "r"(__float_as_uint(a.z)), "r"(__float_as_uint(a.w)),
          "r"(__float_as_uint(b.x)), "r"(__float_as_uint(b.y)));
}

// Permuted fragment-friendly smem indices.
// A element (row=m, col=k) of an m16n8k8 tile: float index so that lane's
// 4 regs {a0,a1,a2,a3} are one contiguous float4.
__device__ __forceinline__ int a_idx(int row, int col, int KS) {
    int mt = row >> 4, r = row & 15, ks = col >> 3, cc = col & 7;
    int lane = ((r & 7) << 2) | (cc & 3);
    int reg = (r >> 3) | ((cc >> 2) << 1);
    return ((((mt * KS + ks) << 5) + lane) << 2) + reg;
}
// B element (k=kk, n): lane's 2 regs {b0,b1} contiguous float2.
__device__ __forceinline__ int b_idx(int kk, int n, int KS) {
    int nt = n >> 3, g = n & 7, ks = kk >> 3, c = kk & 7;
    int lane = (g << 2) | (c & 3);
    int reg = c >> 2;
    return ((((nt * KS + ks) << 5) + lane) << 1) + reg;
}

// ===================== K1: scores = (Q*0.125) @ K^T =========================
// CTA 128q x 128k, 256 thr = 8 warps (2m x 4n), split-tf32 (3 mma per tile).
// smem: A_hi|A_lo|B_hi|B_lo 4x32KB = 128KB; epilogue stage reuses same space.
#define QK_SMEM 131072

__global__ __launch_bounds__(256) void qk_mma(const float* __restrict__ Q,
                                              const float* __restrict__ Km,
                                              const int* __restrict__ vlen,
                                              float* __restrict__ W) {
    const int kt = blockIdx.x, qt = blockIdx.y, b = blockIdx.z;
    const int L = vlen[b];
    if (L == 0 || kt * 128 >= L) return;

    extern __shared__ char S[];
    float* Ah = (float*)S;
    float* Al = (float*)(S + 32768);
    float* Bh = (float*)(S + 65536);
    float* Bl = (float*)(S + 98304);

    const int t = threadIdx.x;
    const float* Qb = Q + ((size_t)(b * SS + qt * 128)) * DD;
    const float* Kb = Km + ((size_t)(b * SS + kt * 128)) * DD;

    // Stage: split + permute (KS=8 k-steps over D=64)
#pragma unroll
    for (int i = 0; i < 8; i++) {
        int idx = t + i * 256;            // 2048 float4 per matrix
        int row = idx >> 4, c0 = (idx & 15) << 2;
        float4 qv = *(const float4*)&Qb[row * DD + c0];
        float4 kv = *(const float4*)&Kb[row * DD + c0];
        float q[4] = {qv.x * 0.125f, qv.y * 0.125f, qv.z * 0.125f, qv.w * 0.125f};
        float k[4] = {kv.x, kv.y, kv.z, kv.w};
#pragma unroll
        for (int j = 0; j < 4; j++) {
            float2 sq = split_tf32(q[j]);
            int ia = a_idx(row, c0 + j, 8);
            Ah[ia] = sq.x; Al[ia] = sq.y;
            float2 sk = split_tf32(k[j]);
            int ib = b_idx(c0 + j, row, 8);   // contraction k = d, n = key row
            Bh[ib] = sk.x; Bl[ib] = sk.y;
        }
    }
    __syncthreads();

    const int wid = t >> 5, lane = t & 31;
    const int wm = wid >> 2, wn = wid & 3;   // warp covers 64q x 32k

    float acc[4][4][4];
#pragma unroll
    for (int mt = 0; mt < 4; mt++)
#pragma unroll
        for (int nt = 0; nt < 4; nt++)
#pragma unroll
            for (int r = 0; r < 4; r++) acc[mt][nt][r] = 0.0f;

    const float4* Ah4 = (const float4*)Ah;
    const float4* Al4 = (const float4*)Al;
    const float2* Bh2 = (const float2*)Bh;
    const float2* Bl2 = (const float2*)Bl;

#pragma unroll
    for (int s = 0; s < 8; s++) {
        float4 ah[4], al[4];
        float2 bh[4], bl[4];
#pragma unroll
        for (int mt = 0; mt < 4; mt++) {
            int base = (((wm * 4 + mt) * 8 + s) << 5) + lane;
            ah[mt] = Ah4[base]; al[mt] = Al4[base];
        }
#pragma unroll
        for (int nt = 0; nt < 4; nt++) {
            int base = (((wn * 4 + nt) * 8 + s) << 5) + lane;
            bh[nt] = Bh2[base]; bl[nt] = Bl2[base];
        }
#pragma unroll
        for (int mt = 0; mt < 4; mt++)
#pragma unroll
            for (int nt = 0; nt < 4; nt++) {
                mma8(acc[mt][nt], ah[mt], bh[nt]);
                mma8(acc[mt][nt], al[mt], bh[nt]);
                mma8(acc[mt][nt], ah[mt], bl[nt]);
            }
    }
    __syncthreads();

    // Epilogue: stage (pitch 132) -> coalesced STG
    float* Es = (float*)S;
    const int g = lane >> 2, cp = (lane & 3) << 1;
#pragma unroll
    for (int mt = 0; mt < 4; mt++) {
        int row0 = wm * 64 + mt * 16 + g;
#pragma unroll
        for (int nt = 0; nt < 4; nt++) {
            int col0 = wn * 32 + nt * 8 + cp;
            *(float2*)&Es[row0 * 132 + col0] = make_float2(acc[mt][nt][0], acc[mt][nt][1]);
            *(float2*)&Es[(row0 + 8) * 132 + col0] = make_float2(acc[mt][nt][2], acc[mt][nt][3]);
        }
    }
    __syncthreads();

    float* Wp = W + ((size_t)(b * SS + qt * 128)) * SS + (size_t)kt * 128;
    const int c4 = t & 31;
    for (int rr = t >> 5; rr < 128; rr += 8)
        *(float4*)&Wp[(size_t)rr * SS + c4 * 4] = *(float4*)&Es[rr * 132 + c4 * 4];
}

// ===================== K2: softmax (unchanged, validated) ===================
__global__ __launch_bounds__(256) void softmax_kernel(const int* __restrict__ vlen,
                                                      float* __restrict__ W) {
    const int row = blockIdx.x;
    const int b = row >> 11;
    const int L = vlen[b];
    float* Wp = W + (size_t)row * SS;
    const int t = threadIdx.x;

    if (L == 0) {
        const float u = 1.0f / 2048.0f;
        float4 uv = make_float4(u, u, u, u);
        for (int j = t * 4; j < SS; j += 1024) *(float4*)&Wp[j] = uv;
        return;
    }

    __shared__ float es[SS];
    __shared__ float red[8];

    float psum = 0.0f;
    for (int j = t; j < L; j += 256) {
        float e = __expf(Wp[j]);
        es[j] = e;
        psum += e;
    }
#pragma unroll
    for (int o = 16; o; o >>= 1) psum += __shfl_xor_sync(0xffffffffu, psum, o);
    if ((t & 31) == 0) red[t >> 5] = psum;
    __syncthreads();
    float tot = 0.0f;
#pragma unroll
    for (int i = 0; i < 8; i++) tot += red[i];
    const float inv = 1.0f / tot;

    for (int j = t; j < SS; j += 256) {
        Wp[j] = (j < L) ? es[j] * inv : 0.0f;
    }
}

// ===================== K3: O = W @ V ========================================
// CTA 128q x 64d, 8 warps (4m x 2n), kv tiles of 128 (KS=16), split-tf32.
// smem: A_hi|A_lo 2x64KB + B_hi|B_lo 2x32KB = 192KB.
#define PV_SMEM 196608

__global__ __launch_bounds__(256) void pv_mma(const float* __restrict__ W,
                                              const float* __restrict__ V,
                                              const int* __restrict__ vlen,
                                              float* __restrict__ O) {
    const int qt = blockIdx.x, b = blockIdx.y;
    const int L = vlen[b];
    const int nkt = (L == 0) ? 16 : ((L + 127) >> 7);

    extern __shared__ char S[];
    float* Ah = (float*)S;
    float* Al = (float*)(S + 65536);
    float* Bh = (float*)(S + 131072);
    float* Bl = (float*)(S + 163840);

    const int t = threadIdx.x, wid = t >> 5, lane = t & 31;
    const int wm = wid >> 1, wn = wid & 1;   // warp covers 32q x 32d

    const float* Wb = W + ((size_t)(b * SS + qt * 128)) * SS;
    const float* Vb = V + (size_t)b * SS * DD;

    float acc[2][4][4];
#pragma unroll
    for (int mt = 0; mt < 2; mt++)
#pragma unroll
        for (int nt = 0; nt < 4; nt++)
#pragma unroll
            for (int r = 0; r < 4; r++) acc[mt][nt][r] = 0.0f;

    const float4* Ah4 = (const float4*)Ah;
    const float4* Al4 = (const float4*)Al;
    const float2* Bh2 = (const float2*)Bh;
    const float2* Bl2 = (const float2*)Bl;

    for (int kt = 0; kt < nkt; kt++) {
        __syncthreads();  // previous iteration's fragment reads complete
        // Stage W tile 128x128 (A operand), KS=16
#pragma unroll
        for (int i = 0; i < 16; i++) {
            int idx = t + i * 256;
            int row = idx >> 5, c0 = (idx & 31) << 2;
            float4 wv = *(const float4*)&Wb[(size_t)row * SS + kt * 128 + c0];
            float w[4] = {wv.x, wv.y, wv.z, wv.w};
#pragma unroll
            for (int j = 0; j < 4; j++) {
                float2 s = split_tf32(w[j]);
                int ia = a_idx(row, c0 + j, 16);
                Ah[ia] = s.x; Al[ia] = s.y;
            }
        }
        // Stage V tile 128kv x 64d (B operand: k=kv, n=d)
#pragma unroll
        for (int i = 0; i < 8; i++) {
            int idx = t + i * 256;
            int kv = idx >> 4, d0 = (idx & 15) << 2;
            float4 vv = *(const float4*)&Vb[(size_t)(kt * 128 + kv) * DD + d0];
            float v[4] = {vv.x, vv.y, vv.z, vv.w};
#pragma unroll
            for (int j = 0; j < 4; j++) {
                float2 s = split_tf32(v[j]);
                int ib = b_idx(kv, d0 + j, 16);
                Bh[ib] = s.x; Bl[ib] = s.y;
            }
        }
        __syncthreads();

#pragma unroll 4
        for (int s = 0; s < 16; s++) {
            float4 ah[2], al[2];
            float2 bh[4], bl[4];
#pragma unroll
            for (int mt = 0; mt < 2; mt++) {
                int base = (((wm * 2 + mt) * 16 + s) << 5) + lane;
                ah[mt] = Ah4[base]; al[mt] = Al4[base];
            }
#pragma unroll
            for (int nt = 0; nt < 4; nt++) {
                int base = (((wn * 4 + nt) * 16 + s) << 5) + lane;
                bh[nt] = Bh2[base]; bl[nt] = Bl2[base];
            }
#pragma unroll
            for (int mt = 0; mt < 2; mt++)
#pragma unroll
                for (int nt = 0; nt < 4; nt++) {
                    mma8(acc[mt][nt], ah[mt], bh[nt]);
                    mma8(acc[mt][nt], al[mt], bh[nt]);
                    mma8(acc[mt][nt], ah[mt], bl[nt]);
                }
        }
    }

    // Epilogue: direct float2 stores to O (16 MB total, acceptable)
    const int g = lane >> 2, cp = (lane & 3) << 1;
#pragma unroll
    for (int mt = 0; mt < 2; mt++) {
        int row = qt * 128 + wm * 32 + mt * 16 + g;
        float* Op0 = O + ((size_t)(b * SS + row)) * DD;
        float* Op1 = O + ((size_t)(b * SS + row + 8)) * DD;
#pragma unroll
        for (int nt = 0; nt < 4; nt++) {
            int col = wn * 32 + nt * 8 + cp;
            *(float2*)&Op0[col] = make_float2(acc[mt][nt][0], acc[mt][nt][1]);
            *(float2*)&Op1[col] = make_float2(acc[mt][nt][2], acc[mt][nt][3]);
        }
    }
}

// ============================================================================
extern "C" void kernel_launch(void* const* d_in, const int* in_sizes, int n_in,
                              void* d_out, int out_size) {
    const float* Q = (const float*)d_in[0];
    const float* K = (const float*)d_in[1];
    const float* V = (const float*)d_in[2];
    const int* vlen = (const int*)d_in[3];

    const long long BSD = (long long)BB * SS * DD;
    const long long BSS = (long long)BB * SS * SS;

    float* out_o = nullptr;
    float* out_w;
    if ((long long)out_size >= BSD + BSS) {
        out_o = (float*)d_out;
        out_w = (float*)d_out + BSD;
    } else {
        out_w = (float*)d_out;
    }

    cudaFuncSetAttribute(qk_mma, cudaFuncAttributeMaxDynamicSharedMemorySize, QK_SMEM);
    cudaFuncSetAttribute(pv_mma, cudaFuncAttributeMaxDynamicSharedMemorySize, PV_SMEM);

    dim3 g1(SS / 128, SS / 128, BB);
    qk_mma<<<g1, 256, QK_SMEM>>>(Q, K, vlen, out_w);

    softmax_kernel<<<BB * SS, 256>>>(vlen, out_w);

    if (out_o) {
        dim3 g3(SS / 128, BB);
        pv_mma<<<g3, 256, PV_SMEM>>>(out_w, V, vlen, out_o);
    }
}

// round 9
// speedup vs baseline: 1.3631x; 1.3631x over previous
#include <cuda_runtime.h>
#include <cstdint>

#define BB 32
#define SS 2048
#define DD 64

// ===================== tf32 split + mma.sync helpers ========================
__device__ __forceinline__ void split_tf32(float x, float& hi, float& lo) {
    uint32_t h;
    asm("cvt.rna.tf32.f32 %0, %1;" : "=r"(h) : "f"(x));
    hi = __uint_as_float(h);
    float rem = x - hi;
    uint32_t l;
    asm("cvt.rna.tf32.f32 %0, %1;" : "=r"(l) : "f"(rem));
    lo = __uint_as_float(l);
}
__device__ __forceinline__ void split4(float4 v, float4& h, float4& l) {
    split_tf32(v.x, h.x, l.x); split_tf32(v.y, h.y, l.y);
    split_tf32(v.z, h.z, l.z); split_tf32(v.w, h.w, l.w);
}
__device__ __forceinline__ void split2(float2 v, float2& h, float2& l) {
    split_tf32(v.x, h.x, l.x); split_tf32(v.y, h.y, l.y);
}

// D += A(16x8 tf32) * B(8x8 tf32), m16n8k8
__device__ __forceinline__ void mma8(float* c, float4 a, float2 b) {
    asm volatile(
        "mma.sync.aligned.m16n8k8.row.col.f32.tf32.tf32.f32 "
        "{%0,%1,%2,%3}, {%4,%5,%6,%7}, {%8,%9}, {%0,%1,%2,%3};"
        : "+f"(c[0]), "+f"(c[1]), "+f"(c[2]), "+f"(c[3])
        : "r"(__float_as_uint(a.x)), "r"(__float_as_uint(a.y)),
          "r"(__float_as_uint(a.z)), "r"(__float_as_uint(a.w)),
          "r"(__float_as_uint(b.x)), "r"(__float_as_uint(b.y)));
}

// Fragment-permuted smem float indices (validated R8, rel_err 5e-6).
__device__ __forceinline__ int a_idx(int row, int col, int KS) {
    int mt = row >> 4, r = row & 15, ks = col >> 3, cc = col & 7;
    int lane = ((r & 7) << 2) | (cc & 3);
    int reg = (r >> 3) | ((cc >> 2) << 1);
    return ((((mt * KS + ks) << 5) + lane) << 2) + reg;
}
__device__ __forceinline__ int b_idx(int kk, int n, int KS) {
    int nt = n >> 3, g = n & 7, ks = kk >> 3, c = kk & 7;
    int lane = (g << 2) | (c & 3);
    int reg = c >> 2;
    return ((((nt * KS + ks) << 5) + lane) << 1) + reg;
}

// ===================== K1: scores = (Q*0.125) @ K^T =========================
// CTA 128q x 128k, 8 warps (2m x 4n). fp32 staged once (A 32K + B 32K),
// split to tf32 hi/lo in registers after LDS. Epilogue stage reuses smem.
#define QK_SMEM 67584  // max(64KB frags, 128*132*4 epilogue stage)

__global__ __launch_bounds__(256, 2) void qk_mma(const float* __restrict__ Q,
                                                 const float* __restrict__ Km,
                                                 const int* __restrict__ vlen,
                                                 float* __restrict__ W) {
    const int kt = blockIdx.x, qt = blockIdx.y, b = blockIdx.z;
    const int L = vlen[b];
    if (L == 0 || kt * 128 >= L) return;

    extern __shared__ char S[];
    float* Af = (float*)S;             // 8192 floats
    float* Bf = (float*)(S + 32768);   // 8192 floats

    const int t = threadIdx.x;
    const float* Qb = Q + ((size_t)(b * SS + qt * 128)) * DD;
    const float* Kb = Km + ((size_t)(b * SS + kt * 128)) * DD;

#pragma unroll
    for (int i = 0; i < 8; i++) {
        int idx = t + i * 256;
        int row = idx >> 4, c0 = (idx & 15) << 2;
        float4 qv = *(const float4*)&Qb[row * DD + c0];
        float4 kv = *(const float4*)&Kb[row * DD + c0];
        Af[a_idx(row, c0 + 0, 8)] = qv.x * 0.125f;
        Af[a_idx(row, c0 + 1, 8)] = qv.y * 0.125f;
        Af[a_idx(row, c0 + 2, 8)] = qv.z * 0.125f;
        Af[a_idx(row, c0 + 3, 8)] = qv.w * 0.125f;
        Bf[b_idx(c0 + 0, row, 8)] = kv.x;
        Bf[b_idx(c0 + 1, row, 8)] = kv.y;
        Bf[b_idx(c0 + 2, row, 8)] = kv.z;
        Bf[b_idx(c0 + 3, row, 8)] = kv.w;
    }
    __syncthreads();

    const int wid = t >> 5, lane = t & 31;
    const int wm = wid >> 2, wn = wid & 3;

    float acc[4][4][4];
#pragma unroll
    for (int mt = 0; mt < 4; mt++)
#pragma unroll
        for (int nt = 0; nt < 4; nt++)
#pragma unroll
            for (int r = 0; r < 4; r++) acc[mt][nt][r] = 0.0f;

    const float4* Af4 = (const float4*)Af;
    const float2* Bf2 = (const float2*)Bf;

#pragma unroll
    for (int s = 0; s < 8; s++) {
        float2 bh[4], bl[4];
#pragma unroll
        for (int nt = 0; nt < 4; nt++) {
            float2 bv = Bf2[(((wn * 4 + nt) * 8 + s) << 5) + lane];
            split2(bv, bh[nt], bl[nt]);
        }
#pragma unroll
        for (int mt = 0; mt < 4; mt++) {
            float4 av = Af4[(((wm * 4 + mt) * 8 + s) << 5) + lane];
            float4 ah, al;
            split4(av, ah, al);
#pragma unroll
            for (int nt = 0; nt < 4; nt++) {
                mma8(acc[mt][nt], ah, bh[nt]);
                mma8(acc[mt][nt], al, bh[nt]);
                mma8(acc[mt][nt], ah, bl[nt]);
            }
        }
    }
    __syncthreads();

    // Epilogue: smem stage (pitch 132) -> coalesced STG
    float* Es = (float*)S;
    const int g = lane >> 2, cp = (lane & 3) << 1;
#pragma unroll
    for (int mt = 0; mt < 4; mt++) {
        int row0 = wm * 64 + mt * 16 + g;
#pragma unroll
        for (int nt = 0; nt < 4; nt++) {
            int col0 = wn * 32 + nt * 8 + cp;
            *(float2*)&Es[row0 * 132 + col0] = make_float2(acc[mt][nt][0], acc[mt][nt][1]);
            *(float2*)&Es[(row0 + 8) * 132 + col0] = make_float2(acc[mt][nt][2], acc[mt][nt][3]);
        }
    }
    __syncthreads();

    float* Wp = W + ((size_t)(b * SS + qt * 128)) * SS + (size_t)kt * 128;
    const int c4 = t & 31;
    for (int rr = t >> 5; rr < 128; rr += 8)
        *(float4*)&Wp[(size_t)rr * SS + c4 * 4] = *(float4*)&Es[rr * 132 + c4 * 4];
}

// ===================== K2: softmax (unchanged, validated) ===================
__global__ __launch_bounds__(256) void softmax_kernel(const int* __restrict__ vlen,
                                                      float* __restrict__ W) {
    const int row = blockIdx.x;
    const int b = row >> 11;
    const int L = vlen[b];
    float* Wp = W + (size_t)row * SS;
    const int t = threadIdx.x;

    if (L == 0) {
        const float u = 1.0f / 2048.0f;
        float4 uv = make_float4(u, u, u, u);
        for (int j = t * 4; j < SS; j += 1024) *(float4*)&Wp[j] = uv;
        return;
    }

    __shared__ float es[SS];
    __shared__ float red[8];

    float psum = 0.0f;
    for (int j = t; j < L; j += 256) {
        float e = __expf(Wp[j]);
        es[j] = e;
        psum += e;
    }
#pragma unroll
    for (int o = 16; o; o >>= 1) psum += __shfl_xor_sync(0xffffffffu, psum, o);
    if ((t & 31) == 0) red[t >> 5] = psum;
    __syncthreads();
    float tot = 0.0f;
#pragma unroll
    for (int i = 0; i < 8; i++) tot += red[i];
    const float inv = 1.0f / tot;

    for (int j = t; j < SS; j += 256) {
        Wp[j] = (j < L) ? es[j] * inv : 0.0f;
    }
}

// ===================== K3: O = W @ V ========================================
// CTA 64q x 64d, 8 warps (4m x 2n), kv tiles of 128 (KS=16).
// fp32 staged (W 32K + V 32K = 64KB), register split. 3 CTAs/SM, 1024 CTAs.
#define PV_SMEM 65536

__global__ __launch_bounds__(256, 3) void pv_mma(const float* __restrict__ W,
                                                 const float* __restrict__ V,
                                                 const int* __restrict__ vlen,
                                                 float* __restrict__ O) {
    const int qt = blockIdx.x, b = blockIdx.y;
    const int L = vlen[b];
    const int nkt = (L == 0) ? 16 : ((L + 127) >> 7);

    extern __shared__ char S[];
    float* Af = (float*)S;             // 64x128 permuted, 32KB
    float* Bf = (float*)(S + 32768);   // 128x64 permuted, 32KB

    const int t = threadIdx.x, wid = t >> 5, lane = t & 31;
    const int wm = wid >> 1, wn = wid & 1;  // warp: 16q x 32d

    const float* Wb = W + ((size_t)(b * SS + qt * 64)) * SS;
    const float* Vb = V + (size_t)b * SS * DD;

    float acc[4][4];
#pragma unroll
    for (int nt = 0; nt < 4; nt++)
#pragma unroll
        for (int r = 0; r < 4; r++) acc[nt][r] = 0.0f;

    const float4* Af4 = (const float4*)Af;
    const float2* Bf2 = (const float2*)Bf;

    for (int kt = 0; kt < nkt; kt++) {
        __syncthreads();
        // Stage W tile 64x128 (A operand), KS=16: 2048 float4, 8/thread
#pragma unroll
        for (int i = 0; i < 8; i++) {
            int idx = t + i * 256;
            int row = idx >> 5, c0 = (idx & 31) << 2;
            float4 wv = *(const float4*)&Wb[(size_t)row * SS + kt * 128 + c0];
            Af[a_idx(row, c0 + 0, 16)] = wv.x;
            Af[a_idx(row, c0 + 1, 16)] = wv.y;
            Af[a_idx(row, c0 + 2, 16)] = wv.z;
            Af[a_idx(row, c0 + 3, 16)] = wv.w;
        }
        // Stage V tile 128kv x 64d (B operand), KS=16: 2048 float4, 8/thread
#pragma unroll
        for (int i = 0; i < 8; i++) {
            int idx = t + i * 256;
            int kv = idx >> 4, d0 = (idx & 15) << 2;
            float4 vv = *(const float4*)&Vb[(size_t)(kt * 128 + kv) * DD + d0];
            Bf[b_idx(kv, d0 + 0, 16)] = vv.x;
            Bf[b_idx(kv, d0 + 1, 16)] = vv.y;
            Bf[b_idx(kv, d0 + 2, 16)] = vv.z;
            Bf[b_idx(kv, d0 + 3, 16)] = vv.w;
        }
        __syncthreads();

#pragma unroll 4
        for (int s = 0; s < 16; s++) {
            float4 av = Af4[((wm * 16 + s) << 5) + lane];
            float4 ah, al;
            split4(av, ah, al);
#pragma unroll
            for (int nt = 0; nt < 4; nt++) {
                float2 bv = Bf2[(((wn * 4 + nt) * 16 + s) << 5) + lane];
                float2 bh, bl;
                split2(bv, bh, bl);
                mma8(acc[nt], ah, bh);
                mma8(acc[nt], al, bh);
                mma8(acc[nt], ah, bl);
            }
        }
    }

    // Epilogue: direct float2 stores
    const int g = lane >> 2, cp = (lane & 3) << 1;
    int row = qt * 64 + wm * 16 + g;
    float* Op0 = O + ((size_t)(b * SS + row)) * DD;
    float* Op1 = O + ((size_t)(b * SS + row + 8)) * DD;
#pragma unroll
    for (int nt = 0; nt < 4; nt++) {
        int col = wn * 32 + nt * 8 + cp;
        *(float2*)&Op0[col] = make_float2(acc[nt][0], acc[nt][1]);
        *(float2*)&Op1[col] = make_float2(acc[nt][2], acc[nt][3]);
    }
}

// ============================================================================
extern "C" void kernel_launch(void* const* d_in, const int* in_sizes, int n_in,
                              void* d_out, int out_size) {
    const float* Q = (const float*)d_in[0];
    const float* K = (const float*)d_in[1];
    const float* V = (const float*)d_in[2];
    const int* vlen = (const int*)d_in[3];

    const long long BSD = (long long)BB * SS * DD;
    const long long BSS = (long long)BB * SS * SS;

    float* out_o = nullptr;
    float* out_w;
    if ((long long)out_size >= BSD + BSS) {
        out_o = (float*)d_out;
        out_w = (float*)d_out + BSD;
    } else {
        out_w = (float*)d_out;
    }

    cudaFuncSetAttribute(qk_mma, cudaFuncAttributeMaxDynamicSharedMemorySize, QK_SMEM);
    cudaFuncSetAttribute(pv_mma, cudaFuncAttributeMaxDynamicSharedMemorySize, PV_SMEM);

    dim3 g1(SS / 128, SS / 128, BB);
    qk_mma<<<g1, 256, QK_SMEM>>>(Q, K, vlen, out_w);

    softmax_kernel<<<BB * SS, 256>>>(vlen, out_w);

    if (out_o) {
        dim3 g3(SS / 64, BB);
        pv_mma<<<g3, 256, PV_SMEM>>>(out_w, V, vlen, out_o);
    }
}